// round 8
// baseline (speedup 1.0000x reference)
#include <cuda_runtime.h>
#include <cuda_fp16.h>
#include <cstdint>

// LSTMCell: gates = x@Wx + bx + h@Wh ; i,f,g,o -> (h_new, c_new)
// Virtual GEMM [8192,2048] x [2048,4096]^T (fp16, f32 acc), mma.sync.
// Pre-pass 1: g_Ah[8192,2048] fp16 = concat(x,h), K-major.
// Pre-pass 2: g_Wt[4096,2048] fp16 = W^T, K-major, gate-interleaved rows
//             (row j*4+g) so the LSTM epilogue fuses per CTA.
// Main: 128x256 tile, 64x64 warp tiles, cp.async 3-stage, ldmatrix.x4,
//       mma.sync.m16n8k16, smem regroup + fused LSTM epilogue.

#define B_DIM 8192
#define K_DIM 2048
#define N_DIM 4096
#define H_DIM 1024

#define BM 128
#define BN 256
#define BKH 64                    // K-chunk (halves) = 128 B row
#define NCHUNK (K_DIM / BKH)      // 32
#define THREADS 256
#define STAGES 3

#define A_BYTES (BM * 128)                       // 16384
#define B_BYTES (BN * 128)                       // 32768
#define STAGE_BYTES (A_BYTES + B_BYTES)          // 49152
#define OFF_BIAS (STAGES * STAGE_BYTES)          // 147456
#define SMEM_TOTAL (OFF_BIAS + BN * 4)           // 148480
#define LDE 260                                  // epilogue row pitch (floats)

__device__ __half g_Ah[(size_t)B_DIM * K_DIM];   // 32 MB
__device__ __half g_Wt[(size_t)N_DIM * K_DIM];   // 16 MB

#define SW128(o) ((o) ^ (((o) >> 3) & 0x70))

__device__ __forceinline__ uint32_t smem_u32(const void* p) {
    uint32_t a;
    asm("{ .reg .u64 t; cvta.to.shared.u64 t, %1; cvt.u32.u64 %0, t; }"
        : "=r"(a) : "l"(p));
    return a;
}
__device__ __forceinline__ void cp16(uint32_t dst, const void* src) {
    asm volatile("cp.async.cg.shared.global [%0], [%1], 16;"
                 :: "r"(dst), "l"(src) : "memory");
}
#define CP_COMMIT() asm volatile("cp.async.commit_group;" ::: "memory")

__device__ __forceinline__ void ldsm4(uint32_t& r0, uint32_t& r1,
                                      uint32_t& r2, uint32_t& r3, uint32_t a) {
    asm volatile("ldmatrix.sync.aligned.m8n8.x4.shared.b16 {%0,%1,%2,%3}, [%4];"
                 : "=r"(r0), "=r"(r1), "=r"(r2), "=r"(r3) : "r"(a));
}

// ------------------------------------------------------------- pre-passes
__global__ void conv_A(const float* __restrict__ x, const float* __restrict__ h) {
    int i = blockIdx.x * blockDim.x + threadIdx.x;
    int row = i >> 8;
    int col = (i & 255) * 8;
    const float* src = (col < 1024) ? (x + (size_t)row * 1024 + col)
                                    : (h + (size_t)row * 1024 + (col - 1024));
    float4 v0 = ((const float4*)src)[0];
    float4 v1 = ((const float4*)src)[1];
    __half2 p[4];
    p[0] = __floats2half2_rn(v0.x, v0.y);
    p[1] = __floats2half2_rn(v0.z, v0.w);
    p[2] = __floats2half2_rn(v1.x, v1.y);
    p[3] = __floats2half2_rn(v1.z, v1.w);
    *(uint4*)(g_Ah + (size_t)row * K_DIM + col) = *(uint4*)p;
}

__global__ void transpose_W(const float* __restrict__ Wx, const float* __restrict__ Wh) {
    __shared__ __half t[32][36];
    int g = blockIdx.z;
    int j0 = blockIdx.x * 32, k0 = blockIdx.y * 32;
    int tx = threadIdx.x, ty = threadIdx.y;          // 32 x 8
    #pragma unroll
    for (int i = 0; i < 4; i++) {
        int k = k0 + ty + i * 8;
        const float* src = (k < 1024) ? (Wx + (size_t)k * N_DIM)
                                      : (Wh + (size_t)(k - 1024) * N_DIM);
        t[ty + i * 8][tx] = __float2half_rn(src[g * 1024 + j0 + tx]);
    }
    __syncthreads();
    #pragma unroll
    for (int i = 0; i < 4; i++) {
        int jj = ty + i * 8;
        g_Wt[((size_t)(j0 + jj) * 4 + g) * K_DIM + k0 + tx] = t[tx][jj];
    }
}

// ------------------------------------------------------------- main kernel
__global__ __launch_bounds__(THREADS, 1)
void lstm_main(const float* __restrict__ cin, const float* __restrict__ bx,
               float* __restrict__ out)
{
    extern __shared__ char smem[];
    const uint32_t sb = smem_u32(smem);
    const int tid  = threadIdx.x;
    const int lane = tid & 31;
    const int warp = tid >> 5;
    const int wm   = warp >> 2;       // 0..1  (64-row slab)
    const int wn   = warp & 3;        // 0..3  (64-col slab)
    const int m0 = blockIdx.y * BM;
    const int n0 = blockIdx.x * BN;
    const int jt0 = n0 >> 2;          // 64 units per block

    const int r0 = tid >> 3, c8 = tid & 7;

    const __half* Agm = g_Ah + (size_t)m0 * K_DIM;
    const __half* Bgm = g_Wt + (size_t)n0 * K_DIM;

    float acc[4][8][4];
    #pragma unroll
    for (int i = 0; i < 4; i++)
        #pragma unroll
        for (int j = 0; j < 8; j++)
            #pragma unroll
            for (int k = 0; k < 4; k++) acc[i][j][k] = 0.0f;

    // -- prologue: chunks 0,1 ---------------------------------------------
    #pragma unroll
    for (int pc = 0; pc < 2; pc++) {
        uint32_t Ab = sb + pc * STAGE_BYTES;
        uint32_t Bb = Ab + A_BYTES;
        #pragma unroll
        for (int i = 0; i < 4; i++) {
            int row = r0 + 32 * i;
            uint32_t o = (uint32_t)row * 128 + c8 * 16;
            cp16(Ab + SW128(o), Agm + (size_t)row * K_DIM + pc * BKH + c8 * 8);
        }
        #pragma unroll
        for (int i = 0; i < 8; i++) {
            int row = r0 + 32 * i;
            uint32_t o = (uint32_t)row * 128 + c8 * 16;
            cp16(Bb + SW128(o), Bgm + (size_t)row * K_DIM + pc * BKH + c8 * 8);
        }
        CP_COMMIT();
    }

    // -- main loop --------------------------------------------------------
    for (int kt = 0; kt < NCHUNK; kt++) {
        if (kt + 2 < NCHUNK) {
            const int s = (kt + 2) % STAGES;
            uint32_t Ab = sb + s * STAGE_BYTES;
            uint32_t Bb = Ab + A_BYTES;
            const int ko = (kt + 2) * BKH;
            #pragma unroll
            for (int i = 0; i < 4; i++) {
                int row = r0 + 32 * i;
                uint32_t o = (uint32_t)row * 128 + c8 * 16;
                cp16(Ab + SW128(o), Agm + (size_t)row * K_DIM + ko + c8 * 8);
            }
            #pragma unroll
            for (int i = 0; i < 8; i++) {
                int row = r0 + 32 * i;
                uint32_t o = (uint32_t)row * 128 + c8 * 16;
                cp16(Bb + SW128(o), Bgm + (size_t)row * K_DIM + ko + c8 * 8);
            }
            CP_COMMIT();
            asm volatile("cp.async.wait_group 2;" ::: "memory");
        } else if (kt + 1 < NCHUNK) {
            asm volatile("cp.async.wait_group 1;" ::: "memory");
        } else {
            asm volatile("cp.async.wait_group 0;" ::: "memory");
        }
        __syncthreads();

        const uint32_t Ab = sb + (kt % STAGES) * STAGE_BYTES;
        const uint32_t Bb = Ab + A_BYTES;
        const int q  = lane >> 3;
        const int rr = lane & 7;
        #pragma unroll
        for (int ks = 0; ks < 4; ks++) {        // 4 x k16
            uint32_t a[4][4];
            #pragma unroll
            for (int mt = 0; mt < 4; mt++) {
                int row = wm * 64 + mt * 16 + (q & 1) * 8 + rr;
                uint32_t o = (uint32_t)row * 128 + ks * 32 + (q >> 1) * 16;
                ldsm4(a[mt][0], a[mt][1], a[mt][2], a[mt][3], Ab + SW128(o));
            }
            uint32_t b[4][4];
            #pragma unroll
            for (int np = 0; np < 4; np++) {    // 4 n16 tiles = 64 cols
                int row = wn * 64 + np * 16 + (q >> 1) * 8 + rr;
                uint32_t o = (uint32_t)row * 128 + ks * 32 + (q & 1) * 16;
                ldsm4(b[np][0], b[np][1], b[np][2], b[np][3], Bb + SW128(o));
            }
            #pragma unroll
            for (int mt = 0; mt < 4; mt++)
                #pragma unroll
                for (int nt = 0; nt < 8; nt++) {
                    const uint32_t b0 = b[nt >> 1][(nt & 1) * 2];
                    const uint32_t b1 = b[nt >> 1][(nt & 1) * 2 + 1];
                    asm volatile(
                        "mma.sync.aligned.m16n8k16.row.col.f32.f16.f16.f32 "
                        "{%0,%1,%2,%3}, {%4,%5,%6,%7}, {%8,%9}, {%0,%1,%2,%3};"
                        : "+f"(acc[mt][nt][0]), "+f"(acc[mt][nt][1]),
                          "+f"(acc[mt][nt][2]), "+f"(acc[mt][nt][3])
                        : "r"(a[mt][0]), "r"(a[mt][1]),
                          "r"(a[mt][2]), "r"(a[mt][3]),
                          "r"(b0), "r"(b1));
                }
        }
        __syncthreads();
    }

    // -- epilogue: regroup via smem, fuse LSTM ----------------------------
    float* gsm = (float*)smem;        // [128][LDE]
    {
        const int gr = lane >> 2, gc = lane & 3;
        #pragma unroll
        for (int mt = 0; mt < 4; mt++)
            #pragma unroll
            for (int nt = 0; nt < 8; nt++) {
                int row = wm * 64 + mt * 16 + gr;
                int col = wn * 64 + nt * 8 + gc * 2;
                *(float2*)&gsm[row * LDE + col] =
                    make_float2(acc[mt][nt][0], acc[mt][nt][1]);
                *(float2*)&gsm[(row + 8) * LDE + col] =
                    make_float2(acc[mt][nt][2], acc[mt][nt][3]);
            }
    }
    float* bsm = (float*)(smem + OFF_BIAS);
    if (tid < BN)
        bsm[tid] = bx[(tid & 3) * 1024 + jt0 + (tid >> 2)];
    __syncthreads();

    float* outh = out;
    float* outc = out + (size_t)B_DIM * H_DIM;
    #pragma unroll
    for (int i = 0; i < 32; i++) {
        int o   = tid + i * THREADS;   // 0..8191 = 128 rows x 64 units
        int u   = o & 63;
        int row = o >> 6;
        float4 g4 = *(const float4*)&gsm[row * LDE + u * 4];
        float4 b4 = *(const float4*)&bsm[u * 4];
        float gi = g4.x + b4.x;
        float gf = g4.y + b4.y;
        float gg = g4.z + b4.z;
        float go = g4.w + b4.w;
        float iv = 1.0f / (1.0f + __expf(-gi));
        float fv = 1.0f / (1.0f + __expf(-gf));
        float gv = tanhf(gg);
        float ov = 1.0f / (1.0f + __expf(-go));
        size_t gidx = (size_t)(m0 + row) * H_DIM + jt0 + u;
        float cn = fv * cin[gidx] + iv * gv;
        outh[gidx] = ov * tanhf(cn);
        outc[gidx] = cn;
    }
}

// ------------------------------------------------------------- launch
extern "C" void kernel_launch(void* const* d_in, const int* in_sizes, int n_in,
                              void* d_out, int out_size)
{
    const float* x  = (const float*)d_in[0];
    const float* h  = (const float*)d_in[1];
    const float* c  = (const float*)d_in[2];
    const float* Wx = (const float*)d_in[3];
    const float* bx = (const float*)d_in[4];
    const float* Wh = (const float*)d_in[5];
    float* out = (float*)d_out;

    conv_A<<<(B_DIM * K_DIM / 8) / 256, 256>>>(x, h);
    transpose_W<<<dim3(32, 64, 4), dim3(32, 8)>>>(Wx, Wh);

    cudaFuncSetAttribute(lstm_main,
                         cudaFuncAttributeMaxDynamicSharedMemorySize, SMEM_TOTAL);
    dim3 grid(N_DIM / BN, B_DIM / BM);   // (16, 64)
    lstm_main<<<grid, THREADS, SMEM_TOTAL>>>(c, bx, out);
}

// round 10
// speedup vs baseline: 1.9427x; 1.9427x over previous
#include <cuda_runtime.h>
#include <cuda_fp16.h>
#include <cstdint>

// LSTMCell: gates = x@Wx + bx + h@Wh ; i,f,g,o -> (h_new, c_new)
// Virtual GEMM [8192,2048] x [2048,4096]^T (fp16, f32 acc), mma.sync.
// Pre-pass 1: g_Ah[8192,2048] fp16 = concat(x,h), K-major.
// Pre-pass 2: g_Wt[4096,2048] fp16 = W^T, K-major, gate-interleaved rows
//             (row j*4+g) so the LSTM epilogue fuses per CTA.
// Main: 128x128 tile, 64x32 warp tiles, cp.async 3-stage pipeline with a
//       SINGLE __syncthreads per K-chunk, ldmatrix.x4, mma.sync.m16n8k16,
//       smem regroup + fused LSTM epilogue.  2 CTAs/SM.

#define B_DIM 8192
#define K_DIM 2048
#define N_DIM 4096
#define H_DIM 1024

#define BM 128
#define BN 128
#define BKH 64                    // K-chunk in halves = 128 B rows
#define NCHUNK (K_DIM / BKH)      // 32
#define THREADS 256
#define STAGES 3

#define STAGE_BYTES (BM * 128 + BN * 128)       // 32768
#define OFF_BIAS (STAGES * STAGE_BYTES)         // 98304
#define SMEM_TOTAL (OFF_BIAS + BN * 4)          // 98816
#define LDE 132                                  // epilogue row pitch (floats)

__device__ __half g_Ah[(size_t)B_DIM * K_DIM];  // 32 MB
__device__ __half g_Wt[(size_t)N_DIM * K_DIM];  // 16 MB

#define SW128(o) ((o) ^ (((o) >> 3) & 0x70))

__device__ __forceinline__ uint32_t smem_u32(const void* p) {
    uint32_t a;
    asm("{ .reg .u64 t; cvta.to.shared.u64 t, %1; cvt.u32.u64 %0, t; }"
        : "=r"(a) : "l"(p));
    return a;
}
__device__ __forceinline__ void cp16(uint32_t dst, const void* src) {
    asm volatile("cp.async.cg.shared.global [%0], [%1], 16;"
                 :: "r"(dst), "l"(src) : "memory");
}
#define CP_COMMIT() asm volatile("cp.async.commit_group;" ::: "memory")

__device__ __forceinline__ void ldsm4(uint32_t& r0, uint32_t& r1,
                                      uint32_t& r2, uint32_t& r3, uint32_t a) {
    asm volatile("ldmatrix.sync.aligned.m8n8.x4.shared.b16 {%0,%1,%2,%3}, [%4];"
                 : "=r"(r0), "=r"(r1), "=r"(r2), "=r"(r3) : "r"(a));
}

// ------------------------------------------------------------- pre-passes
__global__ void conv_A(const float* __restrict__ x, const float* __restrict__ h) {
    int i = blockIdx.x * blockDim.x + threadIdx.x;   // B*K/8 threads
    int row = i >> 8;
    int col = (i & 255) * 8;
    const float* src = (col < 1024) ? (x + (size_t)row * 1024 + col)
                                    : (h + (size_t)row * 1024 + (col - 1024));
    float4 v0 = ((const float4*)src)[0];
    float4 v1 = ((const float4*)src)[1];
    __half2 p[4];
    p[0] = __floats2half2_rn(v0.x, v0.y);
    p[1] = __floats2half2_rn(v0.z, v0.w);
    p[2] = __floats2half2_rn(v1.x, v1.y);
    p[3] = __floats2half2_rn(v1.z, v1.w);
    *(uint4*)(g_Ah + (size_t)row * K_DIM + col) = *(uint4*)p;
}

__global__ void transpose_W(const float* __restrict__ Wx, const float* __restrict__ Wh) {
    __shared__ __half t[32][36];
    int g = blockIdx.z;
    int j0 = blockIdx.x * 32, k0 = blockIdx.y * 32;
    int tx = threadIdx.x, ty = threadIdx.y;          // 32 x 8
    #pragma unroll
    for (int i = 0; i < 4; i++) {
        int k = k0 + ty + i * 8;
        const float* src = (k < 1024) ? (Wx + (size_t)k * N_DIM)
                                      : (Wh + (size_t)(k - 1024) * N_DIM);
        t[ty + i * 8][tx] = __float2half_rn(src[g * 1024 + j0 + tx]);
    }
    __syncthreads();
    #pragma unroll
    for (int i = 0; i < 4; i++) {
        int jj = ty + i * 8;
        g_Wt[((size_t)(j0 + jj) * 4 + g) * K_DIM + k0 + tx] = t[tx][jj];
    }
}

// ------------------------------------------------------------- main kernel
__global__ __launch_bounds__(THREADS, 2)
void lstm_main(const float* __restrict__ cin, const float* __restrict__ bx,
               float* __restrict__ out)
{
    extern __shared__ char smem[];
    const uint32_t sb = smem_u32(smem);
    const int tid  = threadIdx.x;
    const int lane = tid & 31;
    const int warp = tid >> 5;
    const int wm   = warp >> 2;       // 0..1  (64-row slab)
    const int wn   = warp & 3;        // 0..3  (32-col slab)
    const int m0 = blockIdx.y * BM;
    const int n0 = blockIdx.x * BN;
    const int jt0 = n0 >> 2;

    const int r0 = tid >> 3, c8 = tid & 7;   // copy map: 32 rows x 8 x 16B

    const __half* Agm = g_Ah + (size_t)m0 * K_DIM;
    const __half* Bgm = g_Wt + (size_t)n0 * K_DIM;

    float acc[4][4][4];
    #pragma unroll
    for (int i = 0; i < 4; i++)
        #pragma unroll
        for (int j = 0; j < 4; j++)
            #pragma unroll
            for (int k = 0; k < 4; k++) acc[i][j][k] = 0.0f;

    // -- pipeline prologue: chunks 0,1 ------------------------------------
    #pragma unroll
    for (int pc = 0; pc < 2; pc++) {
        uint32_t Ab = sb + pc * STAGE_BYTES;
        uint32_t Bb = Ab + BM * 128;
        #pragma unroll
        for (int i = 0; i < 4; i++) {
            int row = r0 + 32 * i;
            uint32_t o = (uint32_t)row * 128 + c8 * 16;
            cp16(Ab + SW128(o), Agm + (size_t)row * K_DIM + pc * BKH + c8 * 8);
            cp16(Bb + SW128(o), Bgm + (size_t)row * K_DIM + pc * BKH + c8 * 8);
        }
        CP_COMMIT();
    }

    // -- main loop: ONE barrier per chunk ---------------------------------
    // Order per kt:
    //   wait_group  (stage kt data landed)
    //   __syncthreads (retires compute(kt-1) -> stage (kt-1)%3 is free)
    //   issue copy(kt+2) into stage (kt+2)%3 == (kt-1)%3   [safe]
    //   compute(kt)
    for (int kt = 0; kt < NCHUNK; kt++) {
        if (kt + 1 < NCHUNK)
            asm volatile("cp.async.wait_group 1;" ::: "memory");
        else
            asm volatile("cp.async.wait_group 0;" ::: "memory");
        __syncthreads();

        if (kt + 2 < NCHUNK) {
            const int s = (kt + 2) % STAGES;
            uint32_t Ab = sb + s * STAGE_BYTES;
            uint32_t Bb = Ab + BM * 128;
            const int ko = (kt + 2) * BKH;
            #pragma unroll
            for (int i = 0; i < 4; i++) {
                int row = r0 + 32 * i;
                uint32_t o = (uint32_t)row * 128 + c8 * 16;
                cp16(Ab + SW128(o), Agm + (size_t)row * K_DIM + ko + c8 * 8);
                cp16(Bb + SW128(o), Bgm + (size_t)row * K_DIM + ko + c8 * 8);
            }
            CP_COMMIT();
        }

        // compute on stage kt%3
        const uint32_t Ab = sb + (kt % STAGES) * STAGE_BYTES;
        const uint32_t Bb = Ab + BM * 128;
        const int q  = lane >> 3;     // matrix index within ldmatrix.x4
        const int rr = lane & 7;
        #pragma unroll
        for (int ks = 0; ks < 4; ks++) {        // 4 x k16 steps
            uint32_t a[4][4];
            #pragma unroll
            for (int mt = 0; mt < 4; mt++) {
                int row = wm * 64 + mt * 16 + (q & 1) * 8 + rr;
                uint32_t o = (uint32_t)row * 128 + ks * 32 + (q >> 1) * 16;
                ldsm4(a[mt][0], a[mt][1], a[mt][2], a[mt][3], Ab + SW128(o));
            }
            uint32_t b[2][4];
            #pragma unroll
            for (int np = 0; np < 2; np++) {    // 2 n-tiles per ldmatrix.x4
                int row = wn * 32 + np * 16 + (q >> 1) * 8 + rr;
                uint32_t o = (uint32_t)row * 128 + ks * 32 + (q & 1) * 16;
                ldsm4(b[np][0], b[np][1], b[np][2], b[np][3], Bb + SW128(o));
            }
            #pragma unroll
            for (int mt = 0; mt < 4; mt++)
                #pragma unroll
                for (int nt = 0; nt < 4; nt++) {
                    const uint32_t b0 = b[nt >> 1][(nt & 1) * 2];
                    const uint32_t b1 = b[nt >> 1][(nt & 1) * 2 + 1];
                    asm volatile(
                        "mma.sync.aligned.m16n8k16.row.col.f32.f16.f16.f32 "
                        "{%0,%1,%2,%3}, {%4,%5,%6,%7}, {%8,%9}, {%0,%1,%2,%3};"
                        : "+f"(acc[mt][nt][0]), "+f"(acc[mt][nt][1]),
                          "+f"(acc[mt][nt][2]), "+f"(acc[mt][nt][3])
                        : "r"(a[mt][0]), "r"(a[mt][1]),
                          "r"(a[mt][2]), "r"(a[mt][3]),
                          "r"(b0), "r"(b1));
                }
        }
    }
    __syncthreads();   // retire last compute before smem reuse (epilogue)

    // -- epilogue: regroup via smem, fuse LSTM ----------------------------
    float* gsm = (float*)smem;        // [128][LDE]
    {
        const int gr = lane >> 2, gc = lane & 3;
        #pragma unroll
        for (int mt = 0; mt < 4; mt++)
            #pragma unroll
            for (int nt = 0; nt < 4; nt++) {
                int row = wm * 64 + mt * 16 + gr;
                int col = wn * 32 + nt * 8 + gc * 2;
                *(float2*)&gsm[row * LDE + col] =
                    make_float2(acc[mt][nt][0], acc[mt][nt][1]);
                *(float2*)&gsm[(row + 8) * LDE + col] =
                    make_float2(acc[mt][nt][2], acc[mt][nt][3]);
            }
    }
    float* bsm = (float*)(smem + OFF_BIAS);
    if (tid < BN)
        bsm[tid] = bx[(tid & 3) * 1024 + jt0 + (tid >> 2)];
    __syncthreads();

    float* outh = out;
    float* outc = out + (size_t)B_DIM * H_DIM;
    #pragma unroll
    for (int i = 0; i < 16; i++) {
        int o   = tid + i * THREADS;   // 0..4095 = 128 rows x 32 units
        int u   = o & 31;
        int row = o >> 5;
        float4 g4 = *(const float4*)&gsm[row * LDE + u * 4];
        float4 b4 = *(const float4*)&bsm[u * 4];
        float gi = g4.x + b4.x;
        float gf = g4.y + b4.y;
        float gg = g4.z + b4.z;
        float go = g4.w + b4.w;
        float iv = 1.0f / (1.0f + __expf(-gi));
        float fv = 1.0f / (1.0f + __expf(-gf));
        float gv = tanhf(gg);
        float ov = 1.0f / (1.0f + __expf(-go));
        size_t gidx = (size_t)(m0 + row) * H_DIM + jt0 + u;
        float cn = fv * cin[gidx] + iv * gv;
        outh[gidx] = ov * tanhf(cn);
        outc[gidx] = cn;
    }
}

// ------------------------------------------------------------- launch
extern "C" void kernel_launch(void* const* d_in, const int* in_sizes, int n_in,
                              void* d_out, int out_size)
{
    const float* x  = (const float*)d_in[0];
    const float* h  = (const float*)d_in[1];
    const float* c  = (const float*)d_in[2];
    const float* Wx = (const float*)d_in[3];
    const float* bx = (const float*)d_in[4];
    const float* Wh = (const float*)d_in[5];
    float* out = (float*)d_out;

    conv_A<<<(B_DIM * K_DIM / 8) / 256, 256>>>(x, h);
    transpose_W<<<dim3(32, 64, 4), dim3(32, 8)>>>(Wx, Wh);

    cudaFuncSetAttribute(lstm_main,
                         cudaFuncAttributeMaxDynamicSharedMemorySize, SMEM_TOTAL);
    dim3 grid(N_DIM / BN, B_DIM / BM);   // (32, 64)
    lstm_main<<<grid, THREADS, SMEM_TOTAL>>>(c, bx, out);
}